// round 9
// baseline (speedup 1.0000x reference)
#include <cuda_runtime.h>
#include <cuda_fp16.h>
#include <cstdint>
#include <cstddef>

// ---------------------------------------------------------------------------
// y[8192, 11008] = x[8192,4096] @ (W_int8 * group_scales)^T + bias.
// dtypes (confirmed round 7): x f32, W int32(int8), scales f32, bias f32, out f32.
// sm_103 (no 'a'): tcgen05 unavailable -> mma.sync HMMA path.
// Pass 0: x f32 -> fp16 scratch.  Pass 1: dequant W -> fp16 scratch.
// Pass 2: 128x256x32 GEMM, warp tile 64x64, ldmatrix fragments,
//         mma.m16n8k16 fp32 accum, 4-stage cp.async, fused bias, f32 out.
// ---------------------------------------------------------------------------

static constexpr int IN_F   = 4096;
static constexpr int OUT_F  = 11008;
static constexpr int M_TOT  = 8192;
static constexpr int GROUPS = 32;

static constexpr int BM = 128;
static constexpr int BN = 256;
static constexpr int BK = 32;
static constexpr int NSTG = 4;
static constexpr int KITERS = IN_F / BK;        // 128
static constexpr int MTILES = M_TOT / BM;       // 64
static constexpr int NTILES = OUT_F / BN;       // 43

static constexpr int ROW_BYTES = (BK + 8) * 2;  // 80 B row stride (pad: conflict-free)
static constexpr int A_BYTES = BM * ROW_BYTES;  // 10240
static constexpr int B_BYTES = BN * ROW_BYTES;  // 20480
static constexpr int STG_BYTES = A_BYTES + B_BYTES;       // 30720
static constexpr int B_OFF = A_BYTES;
static constexpr int SM_TOTAL = NSTG * STG_BYTES;         // 122880

__device__ __half g_wdq[(size_t)OUT_F * IN_F];  // fp16 dequant scratch (~86 MB)
__device__ __half g_xh[(size_t)M_TOT * IN_F];   // fp16 x scratch (~64 MB)

// ---------------- Pass 0: x float32 -> fp16 ---------------------------------

__global__ void xh_kernel(const float* __restrict__ x) {
    size_t t = (size_t)blockIdx.x * blockDim.x + threadIdx.x;
    size_t e = t * 8;
    const float4* x4 = reinterpret_cast<const float4*>(x + e);
    float4 v0 = x4[0];
    float4 v1 = x4[1];
    __half h[8];
    h[0] = __float2half_rn(v0.x); h[1] = __float2half_rn(v0.y);
    h[2] = __float2half_rn(v0.z); h[3] = __float2half_rn(v0.w);
    h[4] = __float2half_rn(v1.x); h[5] = __float2half_rn(v1.y);
    h[6] = __float2half_rn(v1.z); h[7] = __float2half_rn(v1.w);
    *reinterpret_cast<uint4*>(&g_xh[e]) = *reinterpret_cast<const uint4*>(h);
}

// ---------------- Pass 1: dequantize W --------------------------------------

__global__ void dq_kernel(const int* __restrict__ w, const float* __restrict__ sc) {
    size_t t = (size_t)blockIdx.x * blockDim.x + threadIdx.x;
    size_t e = t * 8;
    const int4* w4 = reinterpret_cast<const int4*>(w + e);
    int4 q0 = w4[0];
    int4 q1 = w4[1];
    int o = (int)(e >> 12);
    int g = ((int)e & 4095) >> 7;
    float s = sc[o * GROUPS + g];
    __half h[8];
    h[0] = __float2half_rn(s * (float)q0.x); h[1] = __float2half_rn(s * (float)q0.y);
    h[2] = __float2half_rn(s * (float)q0.z); h[3] = __float2half_rn(s * (float)q0.w);
    h[4] = __float2half_rn(s * (float)q1.x); h[5] = __float2half_rn(s * (float)q1.y);
    h[6] = __float2half_rn(s * (float)q1.z); h[7] = __float2half_rn(s * (float)q1.w);
    *reinterpret_cast<uint4*>(&g_wdq[e]) = *reinterpret_cast<const uint4*>(h);
}

// ---------------- Pass 2: HMMA GEMM ----------------------------------------

#define CP_ASYNC16(sm, gm) \
    asm volatile("cp.async.cg.shared.global [%0], [%1], 16;" :: "r"(sm), "l"(gm))
#define CP_COMMIT() asm volatile("cp.async.commit_group;" ::: "memory")
#define CP_WAIT2()  asm volatile("cp.async.wait_group 2;"  ::: "memory")

#define LDSM4(r0, r1, r2, r3, addr) \
    asm volatile("ldmatrix.sync.aligned.m8n8.x4.shared.b16 {%0,%1,%2,%3}, [%4];" \
        : "=r"(r0), "=r"(r1), "=r"(r2), "=r"(r3) : "r"(addr))

__device__ __forceinline__ uint32_t smem_u32(const void* p) {
    uint32_t a;
    asm("{ .reg .u64 t; cvta.to.shared.u64 t, %1; cvt.u32.u64 %0, t; }"
        : "=r"(a) : "l"(p));
    return a;
}

__device__ __forceinline__ void mma16816(float c[4], uint32_t a0, uint32_t a1,
                                         uint32_t a2, uint32_t a3,
                                         uint32_t b0, uint32_t b1) {
    asm volatile(
        "mma.sync.aligned.m16n8k16.row.col.f32.f16.f16.f32 "
        "{%0,%1,%2,%3}, {%4,%5,%6,%7}, {%8,%9}, {%0,%1,%2,%3};"
        : "+f"(c[0]), "+f"(c[1]), "+f"(c[2]), "+f"(c[3])
        : "r"(a0), "r"(a1), "r"(a2), "r"(a3), "r"(b0), "r"(b1));
}

__global__ void __launch_bounds__(256, 1)
gemm_kernel(const float* __restrict__ bias, float* __restrict__ out) {
    extern __shared__ __align__(16) char smem[];
    const uint32_t sb = smem_u32(smem);
    const int tid = threadIdx.x;
    const int wid = tid >> 5;
    const int lane = tid & 31;
    const int g = lane >> 2;     // accum row group
    const int t = lane & 3;      // accum col pair

    const int bid = blockIdx.x;
    const int mi = bid & (MTILES - 1);   // M fastest: W N-band + x stay L2-hot
    const int ni = bid >> 6;
    const int m0 = mi * BM;
    const int n0 = ni * BN;

    const int wm = (wid >> 2) * 64;      // warp M offset (0,64)
    const int wn = (wid & 3) * 64;       // warp N offset (0..192)

    // ---- cp.async slots: 2 A-chunks + 4 B-chunks of 16B per thread/stage
    const char* gA[2]; uint32_t sA[2];
    #pragma unroll
    for (int r = 0; r < 2; r++) {
        int chunk = r * 256 + tid;
        int row = chunk >> 2, seg = chunk & 3;
        gA[r] = reinterpret_cast<const char*>(g_xh + (size_t)(m0 + row) * IN_F) + seg * 16;
        sA[r] = (uint32_t)(row * ROW_BYTES + seg * 16);
    }
    const char* gB[4]; uint32_t sB[4];
    #pragma unroll
    for (int r = 0; r < 4; r++) {
        int chunk = r * 256 + tid;
        int row = chunk >> 2, seg = chunk & 3;
        gB[r] = reinterpret_cast<const char*>(g_wdq + (size_t)(n0 + row) * IN_F) + seg * 16;
        sB[r] = (uint32_t)(B_OFF + row * ROW_BYTES + seg * 16);
    }

    auto load_stage = [&](int kc) {
        const uint32_t so = (uint32_t)((kc & (NSTG - 1)) * STG_BYTES);
        const size_t ko = (size_t)kc * (BK * 2);
        #pragma unroll
        for (int r = 0; r < 2; r++) CP_ASYNC16(sb + so + sA[r], gA[r] + ko);
        #pragma unroll
        for (int r = 0; r < 4; r++) CP_ASYNC16(sb + so + sB[r], gB[r] + ko);
    };

    // ---- ldmatrix per-lane base addresses (stage 0, ks 0)
    // A (16x16 tile i): lanes 0-15 -> rows, cols 0-7; lanes 16-31 -> cols 8-15.
    uint32_t aAd[4];
    #pragma unroll
    for (int i = 0; i < 4; i++)
        aAd[i] = (uint32_t)((wm + i * 16 + (lane & 15)) * ROW_BYTES + (lane >> 4) * 16);
    // B (two n8k16 tiles per LDSM.x4): q=lane>>3: m0=rows0-7/k0-7, m1=rows0-7/k8-15,
    // m2=rows8-15/k0-7, m3=rows8-15/k8-15.
    uint32_t bAd[4];
    {
        const int q = lane >> 3, lr = lane & 7;
        const int rowoff = ((q >> 1) << 3) + lr;
        const int colb = (q & 1) * 16;
        #pragma unroll
        for (int jp = 0; jp < 4; jp++)
            bAd[jp] = (uint32_t)(B_OFF + (wn + jp * 16 + rowoff) * ROW_BYTES + colb);
    }

    float acc[4][8][4];
    #pragma unroll
    for (int i = 0; i < 4; i++)
        #pragma unroll
        for (int j = 0; j < 8; j++)
            #pragma unroll
            for (int q = 0; q < 4; q++) acc[i][j][q] = 0.0f;

    // ---- prologue: fill 3 of 4 stages
    load_stage(0); CP_COMMIT();
    load_stage(1); CP_COMMIT();
    load_stage(2); CP_COMMIT();

    #pragma unroll 1
    for (int kc = 0; kc < KITERS; ++kc) {
        const uint32_t stg = sb + (uint32_t)((kc & (NSTG - 1)) * STG_BYTES);
        CP_WAIT2();
        __syncthreads();

        if (kc + 3 < KITERS) load_stage(kc + 3);
        CP_COMMIT();

        #pragma unroll
        for (int ks = 0; ks < 2; ks++) {
            const uint32_t ko = (uint32_t)(ks * 32);
            uint32_t b[4][4];
            #pragma unroll
            for (int jp = 0; jp < 4; jp++)
                LDSM4(b[jp][0], b[jp][1], b[jp][2], b[jp][3], stg + bAd[jp] + ko);
            uint32_t a[4][4];
            #pragma unroll
            for (int i = 0; i < 4; i++)
                LDSM4(a[i][0], a[i][1], a[i][2], a[i][3], stg + aAd[i] + ko);
            #pragma unroll
            for (int i = 0; i < 4; i++)
                #pragma unroll
                for (int jp = 0; jp < 4; jp++) {
                    mma16816(acc[i][2 * jp],     a[i][0], a[i][1], a[i][2], a[i][3],
                             b[jp][0], b[jp][1]);
                    mma16816(acc[i][2 * jp + 1], a[i][0], a[i][1], a[i][2], a[i][3],
                             b[jp][2], b[jp][3]);
                }
        }
    }

    // ---- epilogue: bias + float32 stores
    const int m_base = m0 + wm + g;
    const int n_base = n0 + wn + 2 * t;
    #pragma unroll
    for (int j = 0; j < 8; j++) {
        const int cc = n_base + j * 8;
        const float b0f = bias[cc];
        const float b1f = bias[cc + 1];
        #pragma unroll
        for (int i = 0; i < 4; i++) {
            const size_t r0 = (size_t)(m_base + i * 16);
            float2 v0 = make_float2(acc[i][j][0] + b0f, acc[i][j][1] + b1f);
            float2 v1 = make_float2(acc[i][j][2] + b0f, acc[i][j][3] + b1f);
            *reinterpret_cast<float2*>(out + r0 * OUT_F + cc) = v0;
            *reinterpret_cast<float2*>(out + (r0 + 8) * OUT_F + cc) = v1;
        }
    }
}

// ---------------- launch ----------------------------------------------------

extern "C" void kernel_launch(void* const* d_in, const int* in_sizes, int n_in,
                              void* d_out, int out_size) {
    const float* x    = reinterpret_cast<const float*>(d_in[0]);
    const int*   w    = reinterpret_cast<const int*>(d_in[1]);
    const float* sc   = reinterpret_cast<const float*>(d_in[2]);
    const float* bias = reinterpret_cast<const float*>(d_in[3]);
    float*       out  = reinterpret_cast<float*>(d_out);

    xh_kernel<<<(unsigned)((size_t)M_TOT * IN_F / 2048), 256>>>(x);
    dq_kernel<<<(unsigned)((size_t)OUT_F * IN_F / 2048), 256>>>(w, sc);

    cudaFuncSetAttribute(gemm_kernel,
                         cudaFuncAttributeMaxDynamicSharedMemorySize, SM_TOTAL);
    gemm_kernel<<<MTILES * NTILES, 256, SM_TOTAL>>>(bias, out);
}

// round 10
// speedup vs baseline: 1.0905x; 1.0905x over previous
#include <cuda_runtime.h>
#include <cuda_fp16.h>
#include <cstdint>
#include <cstddef>

// ---------------------------------------------------------------------------
// y[8192, 11008] = x[8192,4096] @ (W_int8 * group_scales)^T + bias.
// dtypes (confirmed): x f32, W int32(int8), scales f32, bias f32, out f32.
// sm_103 (no 'a'): tcgen05 unavailable -> mma.sync HMMA path.
// Pass 0 (fused): x f32 -> fp16 scratch  AND  dequant W -> fp16 scratch.
//   (fused into ONE launch so the harness's ncu -s 5 -c 1 capture slot lands
//    on the GEMM, which has been invisible for two rounds)
// Pass 1: 128x128x32 GEMM, warp tile 64x32, ldmatrix fragments, occupancy 2,
//         mma.m16n8k16 fp32 accum, 4-stage cp.async, fused bias, f32 out.
// ---------------------------------------------------------------------------

static constexpr int IN_F   = 4096;
static constexpr int OUT_F  = 11008;
static constexpr int M_TOT  = 8192;
static constexpr int GROUPS = 32;

static constexpr int BM = 128;
static constexpr int BN = 128;
static constexpr int BK = 32;
static constexpr int NSTG = 4;
static constexpr int KITERS = IN_F / BK;        // 128
static constexpr int MTILES = M_TOT / BM;       // 64
static constexpr int NTILES = OUT_F / BN;       // 86

static constexpr int ROW_BYTES = (BK + 8) * 2;  // 80 B row stride (conflict-free)
static constexpr int A_BYTES = BM * ROW_BYTES;  // 10240
static constexpr int B_BYTES = BN * ROW_BYTES;  // 10240
static constexpr int STG_BYTES = A_BYTES + B_BYTES;  // 20480
static constexpr int B_OFF = A_BYTES;
static constexpr int SM_TOTAL = NSTG * STG_BYTES;    // 81920 -> 2 CTAs/SM

__device__ __half g_wdq[(size_t)OUT_F * IN_F];  // fp16 dequant scratch (~86 MB)
__device__ __half g_xh[(size_t)M_TOT * IN_F];   // fp16 x scratch (~64 MB)

// ---------------- Pass 0: fused x-convert + W-dequant -----------------------

static constexpr unsigned XH_BLOCKS = (unsigned)((size_t)M_TOT * IN_F / 2048);  // 16384
static constexpr unsigned DQ_BLOCKS = (unsigned)((size_t)OUT_F * IN_F / 2048);  // 22016

__global__ void prep_kernel(const float* __restrict__ x, const int* __restrict__ w,
                            const float* __restrict__ sc) {
    const unsigned b = blockIdx.x;
    if (b < XH_BLOCKS) {
        size_t t = (size_t)b * blockDim.x + threadIdx.x;
        size_t e = t * 8;
        const float4* x4 = reinterpret_cast<const float4*>(x + e);
        float4 v0 = x4[0];
        float4 v1 = x4[1];
        __half h[8];
        h[0] = __float2half_rn(v0.x); h[1] = __float2half_rn(v0.y);
        h[2] = __float2half_rn(v0.z); h[3] = __float2half_rn(v0.w);
        h[4] = __float2half_rn(v1.x); h[5] = __float2half_rn(v1.y);
        h[6] = __float2half_rn(v1.z); h[7] = __float2half_rn(v1.w);
        *reinterpret_cast<uint4*>(&g_xh[e]) = *reinterpret_cast<const uint4*>(h);
    } else {
        size_t t = (size_t)(b - XH_BLOCKS) * blockDim.x + threadIdx.x;
        size_t e = t * 8;
        const int4* w4 = reinterpret_cast<const int4*>(w + e);
        int4 q0 = w4[0];
        int4 q1 = w4[1];
        int o = (int)(e >> 12);
        int g = ((int)e & 4095) >> 7;
        float s = sc[o * GROUPS + g];
        __half h[8];
        h[0] = __float2half_rn(s * (float)q0.x); h[1] = __float2half_rn(s * (float)q0.y);
        h[2] = __float2half_rn(s * (float)q0.z); h[3] = __float2half_rn(s * (float)q0.w);
        h[4] = __float2half_rn(s * (float)q1.x); h[5] = __float2half_rn(s * (float)q1.y);
        h[6] = __float2half_rn(s * (float)q1.z); h[7] = __float2half_rn(s * (float)q1.w);
        *reinterpret_cast<uint4*>(&g_wdq[e]) = *reinterpret_cast<const uint4*>(h);
    }
}

// ---------------- Pass 1: HMMA GEMM ----------------------------------------

#define CP_ASYNC16(sm, gm) \
    asm volatile("cp.async.cg.shared.global [%0], [%1], 16;" :: "r"(sm), "l"(gm))
#define CP_COMMIT() asm volatile("cp.async.commit_group;" ::: "memory")
#define CP_WAIT2()  asm volatile("cp.async.wait_group 2;"  ::: "memory")

#define LDSM4(r0, r1, r2, r3, addr) \
    asm volatile("ldmatrix.sync.aligned.m8n8.x4.shared.b16 {%0,%1,%2,%3}, [%4];" \
        : "=r"(r0), "=r"(r1), "=r"(r2), "=r"(r3) : "r"(addr))

__device__ __forceinline__ uint32_t smem_u32(const void* p) {
    uint32_t a;
    asm("{ .reg .u64 t; cvta.to.shared.u64 t, %1; cvt.u32.u64 %0, t; }"
        : "=r"(a) : "l"(p));
    return a;
}

__device__ __forceinline__ void mma16816(float c[4], uint32_t a0, uint32_t a1,
                                         uint32_t a2, uint32_t a3,
                                         uint32_t b0, uint32_t b1) {
    asm volatile(
        "mma.sync.aligned.m16n8k16.row.col.f32.f16.f16.f32 "
        "{%0,%1,%2,%3}, {%4,%5,%6,%7}, {%8,%9}, {%0,%1,%2,%3};"
        : "+f"(c[0]), "+f"(c[1]), "+f"(c[2]), "+f"(c[3])
        : "r"(a0), "r"(a1), "r"(a2), "r"(a3), "r"(b0), "r"(b1));
}

__global__ void __launch_bounds__(256, 2)
gemm_kernel(const float* __restrict__ bias, float* __restrict__ out) {
    extern __shared__ __align__(16) char smem[];
    const uint32_t sb = smem_u32(smem);
    const int tid = threadIdx.x;
    const int wid = tid >> 5;
    const int lane = tid & 31;
    const int g = lane >> 2;     // accum row group
    const int t = lane & 3;      // accum col pair

    const int bid = blockIdx.x;
    const int mi = bid & (MTILES - 1);   // M fastest: W N-band + x stay L2-hot
    const int ni = bid >> 6;
    const int m0 = mi * BM;
    const int n0 = ni * BN;

    const int wm = (wid >> 2) * 64;      // warp M offset (0,64)
    const int wn = (wid & 3) * 32;       // warp N offset (0..96)

    // ---- cp.async slots: 2 A-chunks + 2 B-chunks of 16B per thread/stage
    const char* gA[2]; uint32_t sA[2];
    const char* gB[2]; uint32_t sB[2];
    #pragma unroll
    for (int r = 0; r < 2; r++) {
        int chunk = r * 256 + tid;
        int row = chunk >> 2, seg = chunk & 3;
        gA[r] = reinterpret_cast<const char*>(g_xh + (size_t)(m0 + row) * IN_F) + seg * 16;
        sA[r] = (uint32_t)(row * ROW_BYTES + seg * 16);
        gB[r] = reinterpret_cast<const char*>(g_wdq + (size_t)(n0 + row) * IN_F) + seg * 16;
        sB[r] = (uint32_t)(B_OFF + row * ROW_BYTES + seg * 16);
    }

    auto load_stage = [&](int kc) {
        const uint32_t so = (uint32_t)((kc & (NSTG - 1)) * STG_BYTES);
        const size_t ko = (size_t)kc * (BK * 2);
        #pragma unroll
        for (int r = 0; r < 2; r++) {
            CP_ASYNC16(sb + so + sA[r], gA[r] + ko);
            CP_ASYNC16(sb + so + sB[r], gB[r] + ko);
        }
    };

    // ---- ldmatrix per-lane base addresses
    // A (16x16 tile i): rows wm+i*16+(lane&15), 16B col half (lane>>4).
    uint32_t aAd[4];
    #pragma unroll
    for (int i = 0; i < 4; i++)
        aAd[i] = (uint32_t)((wm + i * 16 + (lane & 15)) * ROW_BYTES + (lane >> 4) * 16);
    // B (n16k16 per LDSM.x4): validated mapping from round 9.
    uint32_t bAd[2];
    {
        const int q = lane >> 3, lr = lane & 7;
        const int rowoff = ((q >> 1) << 3) + lr;
        const int colb = (q & 1) * 16;
        #pragma unroll
        for (int jp = 0; jp < 2; jp++)
            bAd[jp] = (uint32_t)(B_OFF + (wn + jp * 16 + rowoff) * ROW_BYTES + colb);
    }

    float acc[4][4][4];
    #pragma unroll
    for (int i = 0; i < 4; i++)
        #pragma unroll
        for (int j = 0; j < 4; j++)
            #pragma unroll
            for (int q = 0; q < 4; q++) acc[i][j][q] = 0.0f;

    // ---- prologue: fill 3 of 4 stages
    load_stage(0); CP_COMMIT();
    load_stage(1); CP_COMMIT();
    load_stage(2); CP_COMMIT();

    #pragma unroll 1
    for (int kc = 0; kc < KITERS; ++kc) {
        const uint32_t stg = sb + (uint32_t)((kc & (NSTG - 1)) * STG_BYTES);
        CP_WAIT2();
        __syncthreads();

        if (kc + 3 < KITERS) load_stage(kc + 3);
        CP_COMMIT();

        #pragma unroll
        for (int ks = 0; ks < 2; ks++) {
            const uint32_t ko = (uint32_t)(ks * 32);
            uint32_t b[2][4];
            #pragma unroll
            for (int jp = 0; jp < 2; jp++)
                LDSM4(b[jp][0], b[jp][1], b[jp][2], b[jp][3], stg + bAd[jp] + ko);
            uint32_t a[4][4];
            #pragma unroll
            for (int i = 0; i < 4; i++)
                LDSM4(a[i][0], a[i][1], a[i][2], a[i][3], stg + aAd[i] + ko);
            #pragma unroll
            for (int i = 0; i < 4; i++)
                #pragma unroll
                for (int jp = 0; jp < 2; jp++) {
                    mma16816(acc[i][2 * jp],     a[i][0], a[i][1], a[i][2], a[i][3],
                             b[jp][0], b[jp][1]);
                    mma16816(acc[i][2 * jp + 1], a[i][0], a[i][1], a[i][2], a[i][3],
                             b[jp][2], b[jp][3]);
                }
        }
    }

    // ---- epilogue: bias + float32 stores
    const int m_base = m0 + wm + g;
    const int n_base = n0 + wn + 2 * t;
    #pragma unroll
    for (int j = 0; j < 4; j++) {
        const int cc = n_base + j * 8;
        const float b0f = bias[cc];
        const float b1f = bias[cc + 1];
        #pragma unroll
        for (int i = 0; i < 4; i++) {
            const size_t r0 = (size_t)(m_base + i * 16);
            float2 v0 = make_float2(acc[i][j][0] + b0f, acc[i][j][1] + b1f);
            float2 v1 = make_float2(acc[i][j][2] + b0f, acc[i][j][3] + b1f);
            *reinterpret_cast<float2*>(out + r0 * OUT_F + cc) = v0;
            *reinterpret_cast<float2*>(out + (r0 + 8) * OUT_F + cc) = v1;
        }
    }
}

// ---------------- launch ----------------------------------------------------

extern "C" void kernel_launch(void* const* d_in, const int* in_sizes, int n_in,
                              void* d_out, int out_size) {
    const float* x    = reinterpret_cast<const float*>(d_in[0]);
    const int*   w    = reinterpret_cast<const int*>(d_in[1]);
    const float* sc   = reinterpret_cast<const float*>(d_in[2]);
    const float* bias = reinterpret_cast<const float*>(d_in[3]);
    float*       out  = reinterpret_cast<float*>(d_out);

    prep_kernel<<<XH_BLOCKS + DQ_BLOCKS, 256>>>(x, w, sc);

    cudaFuncSetAttribute(gemm_kernel,
                         cudaFuncAttributeMaxDynamicSharedMemorySize, SM_TOTAL);
    gemm_kernel<<<MTILES * NTILES, 256, SM_TOTAL>>>(bias, out);
}

// round 11
// speedup vs baseline: 1.3106x; 1.2018x over previous
#include <cuda_runtime.h>
#include <cuda_fp16.h>
#include <cstdint>
#include <cstddef>

// ---------------------------------------------------------------------------
// y[8192, 11008] = x[8192,4096] @ (W_int8 * group_scales)^T + bias.
// dtypes (confirmed): x f32, W int32(int8), scales f32, bias f32, out f32.
// sm_103 (no 'a'): tcgen05 unavailable -> mma.sync HMMA (measured rt~7.4).
// Pass 0 (fused): x f32 -> fp16 scratch AND dequant W -> fp16 scratch.
// Pass 1: 128x128x64 GEMM, warp tile 64x32, ldmatrix, occupancy 2,
//         3-stage cp.async, software-pipelined fragment double-buffering
//         (LDSM for step s+1 issues under MMAs of step s), 64 barriers total.
// ---------------------------------------------------------------------------

static constexpr int IN_F   = 4096;
static constexpr int OUT_F  = 11008;
static constexpr int M_TOT  = 8192;
static constexpr int GROUPS = 32;

static constexpr int BM = 128;
static constexpr int BN = 128;
static constexpr int BK = 64;
static constexpr int NSTG = 3;
static constexpr int KITERS = IN_F / BK;        // 64
static constexpr int MTILES = M_TOT / BM;       // 64
static constexpr int NTILES = OUT_F / BN;       // 86

static constexpr int ROW_BYTES = (BK + 8) * 2;  // 144 B row stride (conflict-free)
static constexpr int A_BYTES = BM * ROW_BYTES;  // 18432
static constexpr int B_BYTES = BN * ROW_BYTES;  // 18432
static constexpr int STG_BYTES = A_BYTES + B_BYTES;  // 36864
static constexpr int B_OFF = A_BYTES;
static constexpr int SM_TOTAL = NSTG * STG_BYTES;    // 110592 -> 2 CTAs/SM

__device__ __half g_wdq[(size_t)OUT_F * IN_F];  // fp16 dequant scratch (~86 MB)
__device__ __half g_xh[(size_t)M_TOT * IN_F];   // fp16 x scratch (~64 MB)

// ---------------- Pass 0: fused x-convert + W-dequant -----------------------

static constexpr unsigned XH_BLOCKS = (unsigned)((size_t)M_TOT * IN_F / 2048);  // 16384
static constexpr unsigned DQ_BLOCKS = (unsigned)((size_t)OUT_F * IN_F / 2048);  // 22016

__global__ void prep_kernel(const float* __restrict__ x, const int* __restrict__ w,
                            const float* __restrict__ sc) {
    const unsigned b = blockIdx.x;
    if (b < XH_BLOCKS) {
        size_t t = (size_t)b * blockDim.x + threadIdx.x;
        size_t e = t * 8;
        const float4* x4 = reinterpret_cast<const float4*>(x + e);
        float4 v0 = x4[0];
        float4 v1 = x4[1];
        __half h[8];
        h[0] = __float2half_rn(v0.x); h[1] = __float2half_rn(v0.y);
        h[2] = __float2half_rn(v0.z); h[3] = __float2half_rn(v0.w);
        h[4] = __float2half_rn(v1.x); h[5] = __float2half_rn(v1.y);
        h[6] = __float2half_rn(v1.z); h[7] = __float2half_rn(v1.w);
        *reinterpret_cast<uint4*>(&g_xh[e]) = *reinterpret_cast<const uint4*>(h);
    } else {
        size_t t = (size_t)(b - XH_BLOCKS) * blockDim.x + threadIdx.x;
        size_t e = t * 8;
        const int4* w4 = reinterpret_cast<const int4*>(w + e);
        int4 q0 = w4[0];
        int4 q1 = w4[1];
        int o = (int)(e >> 12);
        int g = ((int)e & 4095) >> 7;
        float s = sc[o * GROUPS + g];
        __half h[8];
        h[0] = __float2half_rn(s * (float)q0.x); h[1] = __float2half_rn(s * (float)q0.y);
        h[2] = __float2half_rn(s * (float)q0.z); h[3] = __float2half_rn(s * (float)q0.w);
        h[4] = __float2half_rn(s * (float)q1.x); h[5] = __float2half_rn(s * (float)q1.y);
        h[6] = __float2half_rn(s * (float)q1.z); h[7] = __float2half_rn(s * (float)q1.w);
        *reinterpret_cast<uint4*>(&g_wdq[e]) = *reinterpret_cast<const uint4*>(h);
    }
}

// ---------------- Pass 1: HMMA GEMM ----------------------------------------

#define CP_ASYNC16(sm, gm) \
    asm volatile("cp.async.cg.shared.global [%0], [%1], 16;" :: "r"(sm), "l"(gm))
#define CP_COMMIT() asm volatile("cp.async.commit_group;" ::: "memory")
#define CP_WAIT1()  asm volatile("cp.async.wait_group 1;"  ::: "memory")

#define LDSM4(r0, r1, r2, r3, addr) \
    asm volatile("ldmatrix.sync.aligned.m8n8.x4.shared.b16 {%0,%1,%2,%3}, [%4];" \
        : "=r"(r0), "=r"(r1), "=r"(r2), "=r"(r3) : "r"(addr))

__device__ __forceinline__ uint32_t smem_u32(const void* p) {
    uint32_t a;
    asm("{ .reg .u64 t; cvta.to.shared.u64 t, %1; cvt.u32.u64 %0, t; }"
        : "=r"(a) : "l"(p));
    return a;
}

__device__ __forceinline__ void mma16816(float c[4], uint32_t a0, uint32_t a1,
                                         uint32_t a2, uint32_t a3,
                                         uint32_t b0, uint32_t b1) {
    asm volatile(
        "mma.sync.aligned.m16n8k16.row.col.f32.f16.f16.f32 "
        "{%0,%1,%2,%3}, {%4,%5,%6,%7}, {%8,%9}, {%0,%1,%2,%3};"
        : "+f"(c[0]), "+f"(c[1]), "+f"(c[2]), "+f"(c[3])
        : "r"(a0), "r"(a1), "r"(a2), "r"(a3), "r"(b0), "r"(b1));
}

__global__ void __launch_bounds__(256, 2)
gemm_kernel(const float* __restrict__ bias, float* __restrict__ out) {
    extern __shared__ __align__(16) char smem[];
    const uint32_t sb = smem_u32(smem);
    const int tid = threadIdx.x;
    const int wid = tid >> 5;
    const int lane = tid & 31;
    const int g = lane >> 2;     // accum row group
    const int t = lane & 3;      // accum col pair

    const int bid = blockIdx.x;
    const int mi = bid & (MTILES - 1);   // M fastest: W N-band + x stay L2-hot
    const int ni = bid >> 6;
    const int m0 = mi * BM;
    const int n0 = ni * BN;

    const int wm = (wid >> 2) * 64;      // warp M offset (0,64)
    const int wn = (wid & 3) * 32;       // warp N offset (0..96)

    // ---- cp.async slots: 4 A-chunks + 4 B-chunks of 16B per thread/stage
    // chunk = r*256 + tid; row = chunk>>3 (0..127); seg = chunk&7 (16B column)
    const char* gA[4]; uint32_t sA[4];
    const char* gB[4]; uint32_t sB[4];
    #pragma unroll
    for (int r = 0; r < 4; r++) {
        int chunk = r * 256 + tid;
        int row = chunk >> 3, seg = chunk & 7;
        gA[r] = reinterpret_cast<const char*>(g_xh + (size_t)(m0 + row) * IN_F) + seg * 16;
        sA[r] = (uint32_t)(row * ROW_BYTES + seg * 16);
        gB[r] = reinterpret_cast<const char*>(g_wdq + (size_t)(n0 + row) * IN_F) + seg * 16;
        sB[r] = (uint32_t)(B_OFF + row * ROW_BYTES + seg * 16);
    }

    auto load_stage = [&](int kc) {
        const uint32_t so = (uint32_t)((kc % NSTG) * STG_BYTES);
        const size_t ko = (size_t)kc * (BK * 2);
        #pragma unroll
        for (int r = 0; r < 4; r++) {
            CP_ASYNC16(sb + so + sA[r], gA[r] + ko);
            CP_ASYNC16(sb + so + sB[r], gB[r] + ko);
        }
    };

    // ---- ldmatrix per-lane base addresses (within a stage)
    uint32_t aAd[4];
    #pragma unroll
    for (int i = 0; i < 4; i++)
        aAd[i] = (uint32_t)((wm + i * 16 + (lane & 15)) * ROW_BYTES + (lane >> 4) * 16);
    uint32_t bAd[2];
    {
        const int q = lane >> 3, lr = lane & 7;
        const int rowoff = ((q >> 1) << 3) + lr;
        const int colb = (q & 1) * 16;
        #pragma unroll
        for (int jp = 0; jp < 2; jp++)
            bAd[jp] = (uint32_t)(B_OFF + (wn + jp * 16 + rowoff) * ROW_BYTES + colb);
    }

    float acc[4][4][4];
    #pragma unroll
    for (int i = 0; i < 4; i++)
        #pragma unroll
        for (int j = 0; j < 4; j++)
            #pragma unroll
            for (int q = 0; q < 4; q++) acc[i][j][q] = 0.0f;

    // ---- prologue: fill 2 of 3 stages
    load_stage(0); CP_COMMIT();
    load_stage(1); CP_COMMIT();

    #pragma unroll 1
    for (int kc = 0; kc < KITERS; ++kc) {
        CP_WAIT1();            // stage kc resident
        __syncthreads();       // everyone done reading stage being overwritten

        if (kc + 2 < KITERS) load_stage(kc + 2);
        CP_COMMIT();

        const uint32_t stg = sb + (uint32_t)((kc % NSTG) * STG_BYTES);

        // software-pipelined fragments: 2-deep A (8 regs) and B (16 regs)
        uint32_t ab[2][4];
        uint32_t bb[2][8];

        // preload ks=0: B then A tile 0
        #pragma unroll
        for (int jp = 0; jp < 2; jp++)
            LDSM4(bb[0][jp * 4 + 0], bb[0][jp * 4 + 1],
                  bb[0][jp * 4 + 2], bb[0][jp * 4 + 3], stg + bAd[jp]);
        LDSM4(ab[0][0], ab[0][1], ab[0][2], ab[0][3], stg + aAd[0]);

        #pragma unroll
        for (int ks = 0; ks < 4; ks++) {
            const uint32_t ko = (uint32_t)(ks * 32);
            uint32_t* bc = bb[ks & 1];
            if (ks < 3) {     // prefetch next ks's B under this ks's MMAs
                uint32_t* bn = bb[(ks + 1) & 1];
                #pragma unroll
                for (int jp = 0; jp < 2; jp++)
                    LDSM4(bn[jp * 4 + 0], bn[jp * 4 + 1],
                          bn[jp * 4 + 2], bn[jp * 4 + 3],
                          stg + bAd[jp] + ko + 32);
            }
            #pragma unroll
            for (int i = 0; i < 4; i++) {
                uint32_t* ac = ab[i & 1];
                uint32_t* an = ab[(i + 1) & 1];
                if (i < 3) {
                    LDSM4(an[0], an[1], an[2], an[3], stg + aAd[i + 1] + ko);
                } else if (ks < 3) {
                    LDSM4(an[0], an[1], an[2], an[3], stg + aAd[0] + ko + 32);
                }
                mma16816(acc[i][0], ac[0], ac[1], ac[2], ac[3], bc[0], bc[1]);
                mma16816(acc[i][1], ac[0], ac[1], ac[2], ac[3], bc[2], bc[3]);
                mma16816(acc[i][2], ac[0], ac[1], ac[2], ac[3], bc[4], bc[5]);
                mma16816(acc[i][3], ac[0], ac[1], ac[2], ac[3], bc[6], bc[7]);
            }
        }
    }

    // ---- epilogue: bias + float32 stores
    const int m_base = m0 + wm + g;
    const int n_base = n0 + wn + 2 * t;
    #pragma unroll
    for (int j = 0; j < 4; j++) {
        const int cc = n_base + j * 8;
        const float b0f = bias[cc];
        const float b1f = bias[cc + 1];
        #pragma unroll
        for (int i = 0; i < 4; i++) {
            const size_t r0 = (size_t)(m_base + i * 16);
            float2 v0 = make_float2(acc[i][j][0] + b0f, acc[i][j][1] + b1f);
            float2 v1 = make_float2(acc[i][j][2] + b0f, acc[i][j][3] + b1f);
            *reinterpret_cast<float2*>(out + r0 * OUT_F + cc) = v0;
            *reinterpret_cast<float2*>(out + (r0 + 8) * OUT_F + cc) = v1;
        }
    }
}

// ---------------- launch ----------------------------------------------------

extern "C" void kernel_launch(void* const* d_in, const int* in_sizes, int n_in,
                              void* d_out, int out_size) {
    const float* x    = reinterpret_cast<const float*>(d_in[0]);
    const int*   w    = reinterpret_cast<const int*>(d_in[1]);
    const float* sc   = reinterpret_cast<const float*>(d_in[2]);
    const float* bias = reinterpret_cast<const float*>(d_in[3]);
    float*       out  = reinterpret_cast<float*>(d_out);

    prep_kernel<<<XH_BLOCKS + DQ_BLOCKS, 256>>>(x, w, sc);

    cudaFuncSetAttribute(gemm_kernel,
                         cudaFuncAttributeMaxDynamicSharedMemorySize, SM_TOTAL);
    gemm_kernel<<<MTILES * NTILES, 256, SM_TOTAL>>>(bias, out);
}

// round 16
// speedup vs baseline: 1.4501x; 1.1064x over previous
#include <cuda_runtime.h>
#include <cuda_fp16.h>
#include <cstdint>
#include <cstddef>

// ---------------------------------------------------------------------------
// y[8192, 11008] = x[8192,4096] @ (W_int8 * group_scales)^T + bias.
// dtypes (confirmed): x f32, W int32(int8), scales f32, bias f32, out f32.
// sm_103 (no 'a'): tcgen05 unavailable -> mma.sync HMMA (measured rt=8).
// Pass 0 (fused): x f32 -> fp16 scratch AND dequant W -> fp16 scratch.
// Pass 1: 128x128x64 GEMM, warp tile 64x32, ldmatrix, occupancy 2, 3-stage
//         cp.async pipeline with __syncthreads (round-11 verified design;
//         the mbarrier ring variant hung — falsified rounds 12-15).
// ROUND-15 reorder: after the barrier, fragment LDSMs issue FIRST and the
//         cp.async burst for stage kc+2 is deferred until after the ks=0
//         compute block, so MMAs start ~100 cyc earlier each iteration.
// ---------------------------------------------------------------------------

static constexpr int IN_F   = 4096;
static constexpr int OUT_F  = 11008;
static constexpr int M_TOT  = 8192;
static constexpr int GROUPS = 32;

static constexpr int BM = 128;
static constexpr int BN = 128;
static constexpr int BK = 64;
static constexpr int NSTG = 3;
static constexpr int KITERS = IN_F / BK;        // 64
static constexpr int MTILES = M_TOT / BM;       // 64
static constexpr int NTILES = OUT_F / BN;       // 86

static constexpr int ROW_BYTES = (BK + 8) * 2;  // 144 B row stride (conflict-free)
static constexpr int A_BYTES = BM * ROW_BYTES;  // 18432
static constexpr int B_BYTES = BN * ROW_BYTES;  // 18432
static constexpr int STG_BYTES = A_BYTES + B_BYTES;  // 36864
static constexpr int B_OFF = A_BYTES;
static constexpr int SM_TOTAL = NSTG * STG_BYTES;    // 110592 -> 2 CTAs/SM

__device__ __half g_wdq[(size_t)OUT_F * IN_F];  // fp16 dequant scratch (~86 MB)
__device__ __half g_xh[(size_t)M_TOT * IN_F];   // fp16 x scratch (~64 MB)

// ---------------- Pass 0: fused x-convert + W-dequant -----------------------

static constexpr unsigned XH_BLOCKS = (unsigned)((size_t)M_TOT * IN_F / 2048);  // 16384
static constexpr unsigned DQ_BLOCKS = (unsigned)((size_t)OUT_F * IN_F / 2048);  // 22016

__global__ void prep_kernel(const float* __restrict__ x, const int* __restrict__ w,
                            const float* __restrict__ sc) {
    const unsigned b = blockIdx.x;
    if (b < XH_BLOCKS) {
        size_t t = (size_t)b * blockDim.x + threadIdx.x;
        size_t e = t * 8;
        const float4* x4 = reinterpret_cast<const float4*>(x + e);
        float4 v0 = x4[0];
        float4 v1 = x4[1];
        __half h[8];
        h[0] = __float2half_rn(v0.x); h[1] = __float2half_rn(v0.y);
        h[2] = __float2half_rn(v0.z); h[3] = __float2half_rn(v0.w);
        h[4] = __float2half_rn(v1.x); h[5] = __float2half_rn(v1.y);
        h[6] = __float2half_rn(v1.z); h[7] = __float2half_rn(v1.w);
        *reinterpret_cast<uint4*>(&g_xh[e]) = *reinterpret_cast<const uint4*>(h);
    } else {
        size_t t = (size_t)(b - XH_BLOCKS) * blockDim.x + threadIdx.x;
        size_t e = t * 8;
        const int4* w4 = reinterpret_cast<const int4*>(w + e);
        int4 q0 = w4[0];
        int4 q1 = w4[1];
        int o = (int)(e >> 12);
        int g = ((int)e & 4095) >> 7;
        float s = sc[o * GROUPS + g];
        __half h[8];
        h[0] = __float2half_rn(s * (float)q0.x); h[1] = __float2half_rn(s * (float)q0.y);
        h[2] = __float2half_rn(s * (float)q0.z); h[3] = __float2half_rn(s * (float)q0.w);
        h[4] = __float2half_rn(s * (float)q1.x); h[5] = __float2half_rn(s * (float)q1.y);
        h[6] = __float2half_rn(s * (float)q1.z); h[7] = __float2half_rn(s * (float)q1.w);
        *reinterpret_cast<uint4*>(&g_wdq[e]) = *reinterpret_cast<const uint4*>(h);
    }
}

// ---------------- Pass 1: HMMA GEMM ----------------------------------------

#define CP_ASYNC16(sm, gm) \
    asm volatile("cp.async.cg.shared.global [%0], [%1], 16;" :: "r"(sm), "l"(gm))
#define CP_COMMIT() asm volatile("cp.async.commit_group;" ::: "memory")
#define CP_WAIT1()  asm volatile("cp.async.wait_group 1;"  ::: "memory")

#define LDSM4(r0, r1, r2, r3, addr) \
    asm volatile("ldmatrix.sync.aligned.m8n8.x4.shared.b16 {%0,%1,%2,%3}, [%4];" \
        : "=r"(r0), "=r"(r1), "=r"(r2), "=r"(r3) : "r"(addr))

__device__ __forceinline__ uint32_t smem_u32(const void* p) {
    uint32_t a;
    asm("{ .reg .u64 t; cvta.to.shared.u64 t, %1; cvt.u32.u64 %0, t; }"
        : "=r"(a) : "l"(p));
    return a;
}

__device__ __forceinline__ void mma16816(float c[4], uint32_t a0, uint32_t a1,
                                         uint32_t a2, uint32_t a3,
                                         uint32_t b0, uint32_t b1) {
    asm volatile(
        "mma.sync.aligned.m16n8k16.row.col.f32.f16.f16.f32 "
        "{%0,%1,%2,%3}, {%4,%5,%6,%7}, {%8,%9}, {%0,%1,%2,%3};"
        : "+f"(c[0]), "+f"(c[1]), "+f"(c[2]), "+f"(c[3])
        : "r"(a0), "r"(a1), "r"(a2), "r"(a3), "r"(b0), "r"(b1));
}

__global__ void __launch_bounds__(256, 2)
gemm_kernel(const float* __restrict__ bias, float* __restrict__ out) {
    extern __shared__ __align__(16) char smem[];
    const uint32_t sb = smem_u32(smem);
    const int tid = threadIdx.x;
    const int wid = tid >> 5;
    const int lane = tid & 31;
    const int g = lane >> 2;
    const int t = lane & 3;

    const int bid = blockIdx.x;
    const int mi = bid & (MTILES - 1);   // M fastest: W N-band + x stay L2-hot
    const int ni = bid >> 6;
    const int m0 = mi * BM;
    const int n0 = ni * BN;

    const int wm = (wid >> 2) * 64;
    const int wn = (wid & 3) * 32;

    // ---- cp.async slots: 4 A + 4 B chunks of 16B per thread/stage
    const char* gA[4]; uint32_t sA[4];
    const char* gB[4]; uint32_t sB[4];
    #pragma unroll
    for (int r = 0; r < 4; r++) {
        int chunk = r * 256 + tid;
        int row = chunk >> 3, seg = chunk & 7;
        gA[r] = reinterpret_cast<const char*>(g_xh + (size_t)(m0 + row) * IN_F) + seg * 16;
        sA[r] = (uint32_t)(row * ROW_BYTES + seg * 16);
        gB[r] = reinterpret_cast<const char*>(g_wdq + (size_t)(n0 + row) * IN_F) + seg * 16;
        sB[r] = (uint32_t)(B_OFF + row * ROW_BYTES + seg * 16);
    }

    auto load_stage = [&](int kc) {
        const uint32_t so = (uint32_t)((kc % NSTG) * STG_BYTES);
        const size_t ko = (size_t)kc * (BK * 2);
        #pragma unroll
        for (int r = 0; r < 4; r++) {
            CP_ASYNC16(sb + so + sA[r], gA[r] + ko);
            CP_ASYNC16(sb + so + sB[r], gB[r] + ko);
        }
    };

    // ---- ldmatrix per-lane base addresses (within a stage)
    uint32_t aAd[4];
    #pragma unroll
    for (int i = 0; i < 4; i++)
        aAd[i] = (uint32_t)((wm + i * 16 + (lane & 15)) * ROW_BYTES + (lane >> 4) * 16);
    uint32_t bAd[2];
    {
        const int q = lane >> 3, lr = lane & 7;
        const int rowoff = ((q >> 1) << 3) + lr;
        const int colb = (q & 1) * 16;
        #pragma unroll
        for (int jp = 0; jp < 2; jp++)
            bAd[jp] = (uint32_t)(B_OFF + (wn + jp * 16 + rowoff) * ROW_BYTES + colb);
    }

    float acc[4][4][4];
    #pragma unroll
    for (int i = 0; i < 4; i++)
        #pragma unroll
        for (int j = 0; j < 4; j++)
            #pragma unroll
            for (int q = 0; q < 4; q++) acc[i][j][q] = 0.0f;

    // ---- prologue: fill 2 of 3 stages
    load_stage(0); CP_COMMIT();
    load_stage(1); CP_COMMIT();

    #pragma unroll 1
    for (int kc = 0; kc < KITERS; ++kc) {
        CP_WAIT1();            // stage kc resident
        __syncthreads();       // all warps done reading stage being overwritten

        const uint32_t stg = sb + (uint32_t)((kc % NSTG) * STG_BYTES);

        // -- fragment preloads FIRST (latency overlaps later issue work)
        uint32_t ab[2][4];
        uint32_t bb[2][8];
        #pragma unroll
        for (int jp = 0; jp < 2; jp++)
            LDSM4(bb[0][jp * 4 + 0], bb[0][jp * 4 + 1],
                  bb[0][jp * 4 + 2], bb[0][jp * 4 + 3], stg + bAd[jp]);
        LDSM4(ab[0][0], ab[0][1], ab[0][2], ab[0][3], stg + aAd[0]);

        // -- ks = 0 block (peeled): MMAs start before any cp.async issue
        {
            const int ks = 0;
            uint32_t* bc = bb[0];
            uint32_t* bn = bb[1];
            #pragma unroll
            for (int jp = 0; jp < 2; jp++)
                LDSM4(bn[jp * 4 + 0], bn[jp * 4 + 1],
                      bn[jp * 4 + 2], bn[jp * 4 + 3], stg + bAd[jp] + 32);
            #pragma unroll
            for (int i = 0; i < 4; i++) {
                uint32_t* ac = ab[i & 1];
                uint32_t* an = ab[(i + 1) & 1];
                if (i < 3) {
                    LDSM4(an[0], an[1], an[2], an[3], stg + aAd[i + 1]);
                } else {
                    LDSM4(an[0], an[1], an[2], an[3], stg + aAd[0] + 32);
                }
                mma16816(acc[i][0], ac[0], ac[1], ac[2], ac[3], bc[0], bc[1]);
                mma16816(acc[i][1], ac[0], ac[1], ac[2], ac[3], bc[2], bc[3]);
                mma16816(acc[i][2], ac[0], ac[1], ac[2], ac[3], bc[4], bc[5]);
                mma16816(acc[i][3], ac[0], ac[1], ac[2], ac[3], bc[6], bc[7]);
            }
            (void)ks;
        }

        // -- deferred producer: fill stage kc+2 while MMAs drain
        if (kc + 2 < KITERS) load_stage(kc + 2);
        CP_COMMIT();           // exactly one commit per iteration (group count)

        // -- ks = 1..3
        #pragma unroll
        for (int ks = 1; ks < 4; ks++) {
            const uint32_t ko = (uint32_t)(ks * 32);
            uint32_t* bc = bb[ks & 1];
            if (ks < 3) {
                uint32_t* bn = bb[(ks + 1) & 1];
                #pragma unroll
                for (int jp = 0; jp < 2; jp++)
                    LDSM4(bn[jp * 4 + 0], bn[jp * 4 + 1],
                          bn[jp * 4 + 2], bn[jp * 4 + 3],
                          stg + bAd[jp] + ko + 32);
            }
            #pragma unroll
            for (int i = 0; i < 4; i++) {
                uint32_t* ac = ab[i & 1];
                uint32_t* an = ab[(i + 1) & 1];
                if (i < 3) {
                    LDSM4(an[0], an[1], an[2], an[3], stg + aAd[i + 1] + ko);
                } else if (ks < 3) {
                    LDSM4(an[0], an[1], an[2], an[3], stg + aAd[0] + ko + 32);
                }
                mma16816(acc[i][0], ac[0], ac[1], ac[2], ac[3], bc[0], bc[1]);
                mma16816(acc[i][1], ac[0], ac[1], ac[2], ac[3], bc[2], bc[3]);
                mma16816(acc[i][2], ac[0], ac[1], ac[2], ac[3], bc[4], bc[5]);
                mma16816(acc[i][3], ac[0], ac[1], ac[2], ac[3], bc[6], bc[7]);
            }
        }
    }

    // ---- epilogue: bias + float32 stores
    const int m_base = m0 + wm + g;
    const int n_base = n0 + wn + 2 * t;
    #pragma unroll
    for (int j = 0; j < 4; j++) {
        const int cc = n_base + j * 8;
        const float b0f = bias[cc];
        const float b1f = bias[cc + 1];
        #pragma unroll
        for (int i = 0; i < 4; i++) {
            const size_t r0 = (size_t)(m_base + i * 16);
            float2 v0 = make_float2(acc[i][j][0] + b0f, acc[i][j][1] + b1f);
            float2 v1 = make_float2(acc[i][j][2] + b0f, acc[i][j][3] + b1f);
            *reinterpret_cast<float2*>(out + r0 * OUT_F + cc) = v0;
            *reinterpret_cast<float2*>(out + (r0 + 8) * OUT_F + cc) = v1;
        }
    }
}

// ---------------- launch ----------------------------------------------------

extern "C" void kernel_launch(void* const* d_in, const int* in_sizes, int n_in,
                              void* d_out, int out_size) {
    const float* x    = reinterpret_cast<const float*>(d_in[0]);
    const int*   w    = reinterpret_cast<const int*>(d_in[1]);
    const float* sc   = reinterpret_cast<const float*>(d_in[2]);
    const float* bias = reinterpret_cast<const float*>(d_in[3]);
    float*       out  = reinterpret_cast<float*>(d_out);

    prep_kernel<<<XH_BLOCKS + DQ_BLOCKS, 256>>>(x, w, sc);

    cudaFuncSetAttribute(gemm_kernel,
                         cudaFuncAttributeMaxDynamicSharedMemorySize, SM_TOTAL);
    gemm_kernel<<<MTILES * NTILES, 256, SM_TOTAL>>>(bias, out);
}